// round 3
// baseline (speedup 1.0000x reference)
#include <cuda_runtime.h>
#include <cstdint>

// out[b,l,d] = sum_{i,j} x0[b,i,d] * x1[b,j,d] * filters[i*64+j, l]
// B=2048, F1=F2=64, D=16, L=16
//
// n = (b,d) column. Block = 2 batches = 32 n. 256 threads = 32 j-groups x 8 n-quads.
// Per-thread: 16 l x 4 n accumulators as 32 f32x2 (fma.rn.f32x2), j-range 2 (hoisted
// into packed registers). Filters streamed through smem with cp.async double
// buffering (8 chunks x 8 i-rows = 32KB). 2 CTAs/SM (82KB smem, <=128 regs).

#define BB 2
#define NT 256
#define BSTR 1040
#define XS (BB * BSTR)            // 2080
#define X1_OFF XS                 // 2080
#define FILT_OFF (2 * XS)         // 4160
#define CH 8192                   // floats per chunk (8 i-rows * 64 j * 16 l)
#define SMEM_FLOATS (FILT_OFF + 2 * CH)    // 20544
#define SMEM_BYTES (SMEM_FLOATS * 4)       // 82176

typedef unsigned long long u64;

__device__ __forceinline__ u64 pk2(float x) {
    u64 r; asm("mov.b64 %0, {%1, %1};" : "=l"(r) : "f"(x)); return r;
}
__device__ __forceinline__ void fma2(u64 &d, u64 a, u64 b) {
    asm("fma.rn.f32x2 %0, %1, %2, %0;" : "+l"(d) : "l"(a), "l"(b));
}
__device__ __forceinline__ u64 mul2(u64 a, u64 b) {
    u64 r; asm("mul.rn.f32x2 %0, %1, %2;" : "=l"(r) : "l"(a), "l"(b)); return r;
}
__device__ __forceinline__ float2 up2(u64 v) {
    float2 r; asm("mov.b64 {%0, %1}, %2;" : "=f"(r.x), "=f"(r.y) : "l"(v)); return r;
}
__device__ __forceinline__ void cp16(uint32_t dst, const void* src) {
    asm volatile("cp.async.cg.shared.global [%0], [%1], 16;" :: "r"(dst), "l"(src));
}
__device__ __forceinline__ void cp_commit() {
    asm volatile("cp.async.commit_group;");
}

__global__ void __launch_bounds__(NT, 2)
efm_kernel(const float* __restrict__ x0g, const float* __restrict__ x1g,
           const float* __restrict__ filtg, float* __restrict__ outg)
{
    extern __shared__ float smem[];
    float* x0s = smem;
    float* x1s = smem + X1_OFF;

    const int tid = threadIdx.x;
    const int b0  = blockIdx.x * BB;

    uint32_t sbase;
    asm("{ .reg .u64 t; cvta.to.shared.u64 t, %1; cvt.u32.u64 %0, t; }"
        : "=r"(sbase) : "l"(smem));

    // ---- Stage x0/x1 (2 batches each) into padded smem ----
    {
        const float4* g0 = (const float4*)(x0g + b0 * 1024);
        const float4* g1 = (const float4*)(x1g + b0 * 1024);
        float4* s0 = (float4*)x0s;
        float4* s1 = (float4*)x1s;
        #pragma unroll
        for (int k = 0; k < 2; k++) {
            int m = tid + k * NT;            // 0..511 float4
            int b = m >> 8, r = m & 255;
            s0[b * (BSTR / 4) + r] = g0[m];
            s1[b * (BSTR / 4) + r] = g1[m];
        }
    }

    // ---- Prefetch filter chunks 0 and 1 ----
    #pragma unroll
    for (int c = 0; c < 2; c++) {
        const float* gsrc = filtg + c * CH;
        uint32_t dst = sbase + (FILT_OFF + c * CH) * 4;
        #pragma unroll
        for (int k = 0; k < 8; k++) {
            int m = tid + k * NT;            // 0..2047 float4
            cp16(dst + m * 16, gsrc + m * 4);
        }
        cp_commit();
    }

    __syncthreads();   // x0s/x1s visible

    const int g  = tid >> 3;        // j-group 0..31 (j = g*2 + jj)
    const int nq = tid & 7;         // n-quad 0..7
    const int b  = nq >> 2;         // local batch 0..1
    const int d0 = (nq & 3) << 2;

    const float* x0p = x0s + b * BSTR + d0;
    const float* x1p = x1s + b * BSTR + d0;

    // ---- Hoist x1 (this thread's 2 j-rows) packed into registers ----
    u64 c2[2][4];
    #pragma unroll
    for (int jj = 0; jj < 2; jj++) {
        float4 cv = *(const float4*)(x1p + (g * 2 + jj) * 16);
        c2[jj][0] = pk2(cv.x); c2[jj][1] = pk2(cv.y);
        c2[jj][2] = pk2(cv.z); c2[jj][3] = pk2(cv.w);
    }

    u64 acc[4][8];
    #pragma unroll
    for (int n = 0; n < 4; n++)
        #pragma unroll
        for (int p = 0; p < 8; p++) acc[n][p] = 0ULL;

    // ---- Main loop: 8 chunks of 8 i-rows, double buffered ----
    for (int ch = 0; ch < 8; ch++) {
        if (ch < 7) asm volatile("cp.async.wait_group 1;");
        else        asm volatile("cp.async.wait_group 0;");
        __syncthreads();

        const float* fs = smem + FILT_OFF + (ch & 1) * CH;

        #pragma unroll 2
        for (int ii = 0; ii < 8; ii++) {
            const int i = ch * 8 + ii;
            const float4 a = *(const float4*)(x0p + i * 16);
            u64 a2[4];
            a2[0] = pk2(a.x); a2[1] = pk2(a.y);
            a2[2] = pk2(a.z); a2[3] = pk2(a.w);
            const float* wb = fs + ii * 1024 + g * 32;   // row (ii*64+g*2), 16 floats/row

            #pragma unroll
            for (int jj = 0; jj < 2; jj++) {
                u64 q[4];
                #pragma unroll
                for (int n = 0; n < 4; n++) q[n] = mul2(a2[n], c2[jj][n]);

                const ulonglong2* wp = (const ulonglong2*)(wb + jj * 16);
                #pragma unroll
                for (int h = 0; h < 2; h++) {
                    ulonglong2 wA = wp[2 * h], wB = wp[2 * h + 1];
                    u64 w[4] = {wA.x, wA.y, wB.x, wB.y};
                    #pragma unroll
                    for (int n = 0; n < 4; n++)
                        #pragma unroll
                        for (int p = 0; p < 4; p++)
                            fma2(acc[n][4 * h + p], w[p], q[n]);
                }
            }
        }

        __syncthreads();   // done reading buf[ch&1] before overwrite
        if (ch + 2 < 8) {
            const float* gsrc = filtg + (ch + 2) * CH;
            uint32_t dst = sbase + (FILT_OFF + (ch & 1) * CH) * 4;
            #pragma unroll
            for (int k = 0; k < 8; k++) {
                int m = tid + k * NT;
                cp16(dst + m * 16, gsrc + m * 4);
            }
            cp_commit();
        }
    }

    // ---- Reduce 32 j-group partials through smem ----
    __syncthreads();
    float* red = smem;   // [g][l][32 n] : g*512 + l*32 + n  (16384 floats)
    #pragma unroll
    for (int p = 0; p < 8; p++)
        #pragma unroll
        for (int n = 0; n < 4; n++) {
            float2 v = up2(acc[n][p]);
            red[g * 512 + (2 * p)     * 32 + nq * 4 + n] = v.x;
            red[g * 512 + (2 * p + 1) * 32 + nq * 4 + n] = v.y;
        }
    __syncthreads();

    #pragma unroll
    for (int k = 0; k < 2; k++) {
        int idx = tid + k * NT;          // 0..511 = 16 l x 32 n
        int l = idx >> 5, n = idx & 31;
        float s = 0.f;
        #pragma unroll
        for (int gg = 0; gg < 32; gg++) s += red[gg * 512 + l * 32 + n];
        outg[(b0 + (n >> 4)) * 256 + l * 16 + (n & 15)] = s;
    }
}

extern "C" void kernel_launch(void* const* d_in, const int* in_sizes, int n_in,
                              void* d_out, int out_size)
{
    const float* x0   = (const float*)d_in[0];   // [2048, 64, 16]
    const float* x1   = (const float*)d_in[1];   // [2048, 64, 16]
    const float* filt = (const float*)d_in[2];   // [1, 4096, 16]
    float* out        = (float*)d_out;           // [2048, 16, 16]

    cudaFuncSetAttribute(efm_kernel, cudaFuncAttributeMaxDynamicSharedMemorySize, SMEM_BYTES);
    efm_kernel<<<2048 / BB, NT, SMEM_BYTES>>>(x0, x1, filt, out);
}

// round 6
// speedup vs baseline: 2.5149x; 2.5149x over previous
#include <cuda_runtime.h>
#include <cuda_bf16.h>
#include <cstdint>

// out[b,l,d] = sum_{i,j} x0[b,i,d] * x1[b,j,d] * filters[i*64+j, l]
// B=2048, F1=F2=64, D=16, L=16
//
// GEMM reformulation on mma.sync (sm_80 PTX -> legacy HMMA, works on sm_100 target):
//   per CTA: 256 n-columns (n = (b,d)). For each of 8 i-blocks:
//     G[n, c] = sum_j x1[j,n] * W[(ib*8 + c>>4)*64 + j, c&15],  c = 0..127
//   computed as M=256(n) x N=128(c) x K=64(j) bf16 MMA, 3-term hi/lo split, fp32 acc.
//   Fragment layout: row=n, col=c; per 8-col ntile i_local = nt>>1 is CONSTANT, so the
//   epilogue  out[l,n] += x0[i,n] * G[n, i*16+l]  folds per-thread from c-fragments
//   (no cross-lane reduction, no smem round trip).
// W is pre-split/pre-packed into per-fragment uint4 {bhi0,bhi1,blo0,blo1} by prep_kernel;
// main loop streams it with cp.async double buffering (8 x 32KB).

#define NT 256
#define X1_OFF 16640                       // floats: x0s [64][260] then x1s [64][260]
#define SMB_OFF 133120                     // bytes: B double buffer 2 x 32KB
#define SMEM_BYTES (SMB_OFF + 65536)       // 198656

__device__ __align__(16) unsigned char g_wbuf[262144];   // 8 ib x 32KB fragment-packed W

// ---------------- helpers ----------------
__device__ __forceinline__ uint32_t smem_u32(const void* p) {
    uint32_t a; asm("{ .reg .u64 t; cvta.to.shared.u64 t, %1; cvt.u32.u64 %0, t; }"
                    : "=r"(a) : "l"(p));
    return a;
}
__device__ __forceinline__ void cp16(uint32_t dst, const void* src) {
    asm volatile("cp.async.cg.shared.global [%0], [%1], 16;" :: "r"(dst), "l"(src));
}
__device__ __forceinline__ uint32_t pkbf(float v0, float v1) {   // low half = v0
    __nv_bfloat162 t = __float22bfloat162_rn(make_float2(v0, v1));
    return *(uint32_t*)&t;
}
__device__ __forceinline__ void split(float v, float& h, float& l) {
    __nv_bfloat16 hb = __float2bfloat16_rn(v);
    h = __bfloat162float(hb);
    l = v - h;
}
__device__ __forceinline__ void mma_bf16(float* c, uint32_t a0, uint32_t a1,
                                         uint32_t a2, uint32_t a3,
                                         uint32_t b0, uint32_t b1) {
    asm("mma.sync.aligned.m16n8k16.row.col.f32.bf16.bf16.f32 "
        "{%0,%1,%2,%3}, {%4,%5,%6,%7}, {%8,%9}, {%0,%1,%2,%3};"
        : "+f"(c[0]), "+f"(c[1]), "+f"(c[2]), "+f"(c[3])
        : "r"(a0), "r"(a1), "r"(a2), "r"(a3), "r"(b0), "r"(b1));
}

// ---------------- prep: W -> bf16 hi/lo, mma-fragment packed ----------------
__global__ void prep_kernel(const float* __restrict__ filt) {
    int idx = blockIdx.x * 256 + threadIdx.x;       // 16384 threads
    int lane = idx & 31;
    int ks   = (idx >> 5) & 3;
    int nt   = (idx >> 7) & 15;
    int ib   = idx >> 11;                            // 0..7
    int np   = lane >> 2;                            // col within ntile
    int cg   = nt * 8 + np;                          // global col 0..127
    int il   = cg >> 4, l = cg & 15;
    int jb   = ks * 16 + (lane & 3) * 2;
    const float* base = filt + (ib * 8 + il) * 64 * 16 + l;
    float f0 = base[jb * 16],       f1 = base[(jb + 1) * 16];
    float f2 = base[(jb + 8) * 16], f3 = base[(jb + 9) * 16];
    float h0, l0, h1, l1, h2, l2, h3, l3;
    split(f0, h0, l0); split(f1, h1, l1); split(f2, h2, l2); split(f3, h3, l3);
    uint4 o;
    o.x = pkbf(h0, h1); o.y = pkbf(h2, h3);          // b_hi (k lo pair, k hi pair)
    o.z = pkbf(l0, l1); o.w = pkbf(l2, l3);          // b_lo
    *(uint4*)(g_wbuf + ib * 32768 + ((nt * 4 + ks) * 32 + lane) * 16) = o;
}

// ---------------- main ----------------
__global__ void __launch_bounds__(NT, 1)
efm_mma_kernel(const float* __restrict__ x0g, const float* __restrict__ x1g,
               float* __restrict__ outg)
{
    extern __shared__ __align__(16) float smem[];
    float* x0s = smem;
    float* x1s = smem + X1_OFF;
    const uint32_t sbase = smem_u32(smem);

    const int tid  = threadIdx.x;
    const int lane = tid & 31, w = tid >> 5;
    const int bb0  = blockIdx.x * 16;                // 16 batches per CTA

    // prologue: cp.async W fragments for ib=0 into buf0
    #pragma unroll
    for (int k = 0; k < 8; k++) {
        int o = (tid + k * NT) * 16;
        cp16(sbase + SMB_OFF + o, g_wbuf + o);
    }
    asm volatile("cp.async.commit_group;");

    // stage x0/x1 -> smem transposed [j or i][n], stride 260
    {
        const float4* g0 = (const float4*)(x0g + bb0 * 1024);
        const float4* g1 = (const float4*)(x1g + bb0 * 1024);
        #pragma unroll
        for (int k = 0; k < 16; k++) {
            int m = tid + k * NT;                    // 0..4095 float4
            int bl = m >> 8, rem = m & 255;
            int j = rem >> 2, nl = bl * 16 + (rem & 3) * 4;
            float4 v0 = g0[m], v1 = g1[m];
            *(float4*)(x0s + j * 260 + nl) = v0;
            *(float4*)(x1s + j * 260 + nl) = v1;
        }
    }
    __syncthreads();

    // A fragments from x1 (hi/lo), 2 m-tiles x 4 k-steps x 4 regs
    uint32_t ah[2][4][4], al[2][4][4];
    {
        const int r0 = lane >> 2, k0 = (lane & 3) * 2;
        #pragma unroll
        for (int mt = 0; mt < 2; mt++)
            #pragma unroll
            for (int ks = 0; ks < 4; ks++)
                #pragma unroll
                for (int p = 0; p < 4; p++) {
                    int row = mt * 128 + w * 16 + r0 + (p & 1) * 8;
                    int kb  = ks * 16 + k0 + (p >> 1) * 8;
                    float v0 = x1s[kb * 260 + row];
                    float v1 = x1s[(kb + 1) * 260 + row];
                    float h0, l0, h1, l1;
                    split(v0, h0, l0); split(v1, h1, l1);
                    ah[mt][ks][p] = pkbf(h0, h1);
                    al[mt][ks][p] = pkbf(l0, l1);
                }
    }

    float acc[2][2][2][2];                           // [mt][lhi][row][e]
    #pragma unroll
    for (int a = 0; a < 2; a++)
        #pragma unroll
        for (int b = 0; b < 2; b++)
            #pragma unroll
            for (int c = 0; c < 2; c++)
                #pragma unroll
                for (int d = 0; d < 2; d++) acc[a][b][c][d] = 0.f;

    const int nloc0 = w * 16 + (lane >> 2);

    for (int ib = 0; ib < 8; ib++) {
        if (ib + 1 < 8) {
            const unsigned char* src = g_wbuf + (ib + 1) * 32768;
            uint32_t dst = sbase + SMB_OFF + ((ib + 1) & 1) * 32768;
            #pragma unroll
            for (int k = 0; k < 8; k++) {
                int o = (tid + k * NT) * 16;
                cp16(dst + o, src + o);
            }
        }
        asm volatile("cp.async.commit_group;");
        asm volatile("cp.async.wait_group 1;");
        __syncthreads();

        const uint4* Bs = (const uint4*)((const unsigned char*)smem + SMB_OFF
                                         + (ib & 1) * 32768);
        float x0v[2][2];
        #pragma unroll 2
        for (int nt = 0; nt < 16; nt++) {
            if ((nt & 1) == 0) {
                int i = ib * 8 + (nt >> 1);
                #pragma unroll
                for (int mt = 0; mt < 2; mt++)
                    #pragma unroll
                    for (int r = 0; r < 2; r++)
                        x0v[mt][r] = x0s[i * 260 + mt * 128 + nloc0 + r * 8];
            }
            float c[2][4] = {{0.f,0.f,0.f,0.f},{0.f,0.f,0.f,0.f}};
            #pragma unroll
            for (int ks = 0; ks < 4; ks++) {
                uint4 bb = Bs[(nt * 4 + ks) * 32 + lane];
                #pragma unroll
                for (int mt = 0; mt < 2; mt++) {
                    mma_bf16(c[mt], ah[mt][ks][0], ah[mt][ks][1], ah[mt][ks][2], ah[mt][ks][3], bb.x, bb.y);
                    mma_bf16(c[mt], ah[mt][ks][0], ah[mt][ks][1], ah[mt][ks][2], ah[mt][ks][3], bb.z, bb.w);
                    mma_bf16(c[mt], al[mt][ks][0], al[mt][ks][1], al[mt][ks][2], al[mt][ks][3], bb.x, bb.y);
                }
            }
            const int lhi = nt & 1;
            #pragma unroll
            for (int mt = 0; mt < 2; mt++) {
                acc[mt][lhi][0][0] += x0v[mt][0] * c[mt][0];
                acc[mt][lhi][0][1] += x0v[mt][0] * c[mt][1];
                acc[mt][lhi][1][0] += x0v[mt][1] * c[mt][2];
                acc[mt][lhi][1][1] += x0v[mt][1] * c[mt][3];
            }
        }
        __syncthreads();
    }

    // output: thread owns 2 mt x 2 rows x 4 l values
    #pragma unroll
    for (int mt = 0; mt < 2; mt++)
        #pragma unroll
        for (int lhi = 0; lhi < 2; lhi++)
            #pragma unroll
            for (int r = 0; r < 2; r++)
                #pragma unroll
                for (int e = 0; e < 2; e++) {
                    int nloc = mt * 128 + nloc0 + r * 8;
                    int l = lhi * 8 + (lane & 3) * 2 + e;
                    outg[(bb0 + (nloc >> 4)) * 256 + l * 16 + (nloc & 15)]
                        = acc[mt][lhi][r][e];
                }
}

extern "C" void kernel_launch(void* const* d_in, const int* in_sizes, int n_in,
                              void* d_out, int out_size)
{
    const float* x0   = (const float*)d_in[0];   // [2048, 64, 16]
    const float* x1   = (const float*)d_in[1];   // [2048, 64, 16]
    const float* filt = (const float*)d_in[2];   // [1, 4096, 16]
    float* out        = (float*)d_out;           // [2048, 16, 16]

    prep_kernel<<<64, 256>>>(filt);
    cudaFuncSetAttribute(efm_mma_kernel, cudaFuncAttributeMaxDynamicSharedMemorySize, SMEM_BYTES);
    efm_mma_kernel<<<128, NT, SMEM_BYTES>>>(x0, x1, out);
}

// round 7
// speedup vs baseline: 2.5167x; 1.0007x over previous
#include <cuda_runtime.h>
#include <cuda_bf16.h>
#include <cstdint>

// out[b,l,d] = sum_{i,j} x0[b,i,d] * x1[b,j,d] * filters[i*64+j, l]
// B=2048, F1=F2=64, D=16, L=16
//
// GEMM reformulation on mma.sync (m16n8k16 bf16, 3-term hi/lo split, fp32 acc).
// Per CTA: 256 n-columns (n=(b,d)); 16 warps x one 16-row m-tile.
// For each of 8 i-blocks: G[n,c] = sum_j x1[j,n]*W[(ib*8+c>>4)*64+j, c&15], c=0..127,
// then per-thread epilogue acc[l] += x0[i,n]*G[n, i*16+l] folds from c-fragments
// (i_local constant per 8-col ntile; no cross-lane reduction).
// nt pairs (2p, 2p+1) share i (same x0 scalars) but keep independent accumulator
// chains c0/c1, interleaved at issue -> 8 MMA chains per SMSP in flight.
// W pre-split/packed to fragment order by prep_kernel; streamed with cp.async
// double buffering (8 x 32KB).

#define NT 512
#define X1_OFF 16640                       // floats: x0s [64][260] then x1s [64][260]
#define SMB_OFF 133120                     // bytes: B double buffer 2 x 32KB
#define SMEM_BYTES (SMB_OFF + 65536)       // 198656

__device__ __align__(16) unsigned char g_wbuf[262144];   // 8 ib x 32KB fragment-packed W

// ---------------- helpers ----------------
__device__ __forceinline__ uint32_t smem_u32(const void* p) {
    uint32_t a; asm("{ .reg .u64 t; cvta.to.shared.u64 t, %1; cvt.u32.u64 %0, t; }"
                    : "=r"(a) : "l"(p));
    return a;
}
__device__ __forceinline__ void cp16(uint32_t dst, const void* src) {
    asm volatile("cp.async.cg.shared.global [%0], [%1], 16;" :: "r"(dst), "l"(src));
}
__device__ __forceinline__ uint32_t pkbf(float v0, float v1) {   // low half = v0
    __nv_bfloat162 t = __float22bfloat162_rn(make_float2(v0, v1));
    return *(uint32_t*)&t;
}
__device__ __forceinline__ void split(float v, float& h, float& l) {
    __nv_bfloat16 hb = __float2bfloat16_rn(v);
    h = __bfloat162float(hb);
    l = v - h;
}
__device__ __forceinline__ void mma_bf16(float* c, const uint32_t* a,
                                         uint32_t b0, uint32_t b1) {
    asm("mma.sync.aligned.m16n8k16.row.col.f32.bf16.bf16.f32 "
        "{%0,%1,%2,%3}, {%4,%5,%6,%7}, {%8,%9}, {%0,%1,%2,%3};"
        : "+f"(c[0]), "+f"(c[1]), "+f"(c[2]), "+f"(c[3])
        : "r"(a[0]), "r"(a[1]), "r"(a[2]), "r"(a[3]), "r"(b0), "r"(b1));
}

// ---------------- prep: W -> bf16 hi/lo, mma-fragment packed ----------------
__global__ void prep_kernel(const float* __restrict__ filt) {
    int idx = blockIdx.x * 256 + threadIdx.x;       // 16384 threads
    int lane = idx & 31;
    int ks   = (idx >> 5) & 3;
    int nt   = (idx >> 7) & 15;
    int ib   = idx >> 11;                            // 0..7
    int np   = lane >> 2;                            // col within ntile
    int cg   = nt * 8 + np;                          // global col 0..127
    int il   = cg >> 4, l = cg & 15;
    int jb   = ks * 16 + (lane & 3) * 2;
    const float* base = filt + (ib * 8 + il) * 64 * 16 + l;
    float f0 = base[jb * 16],       f1 = base[(jb + 1) * 16];
    float f2 = base[(jb + 8) * 16], f3 = base[(jb + 9) * 16];
    float h0, l0, h1, l1, h2, l2, h3, l3;
    split(f0, h0, l0); split(f1, h1, l1); split(f2, h2, l2); split(f3, h3, l3);
    uint4 o;
    o.x = pkbf(h0, h1); o.y = pkbf(h2, h3);          // b_hi (k lo pair, k hi pair)
    o.z = pkbf(l0, l1); o.w = pkbf(l2, l3);          // b_lo
    *(uint4*)(g_wbuf + ib * 32768 + ((nt * 4 + ks) * 32 + lane) * 16) = o;
}

// ---------------- main ----------------
__global__ void __launch_bounds__(NT, 1)
efm_mma_kernel(const float* __restrict__ x0g, const float* __restrict__ x1g,
               float* __restrict__ outg)
{
    extern __shared__ __align__(16) float smem[];
    float* x0s = smem;
    float* x1s = smem + X1_OFF;
    const uint32_t sbase = smem_u32(smem);

    const int tid  = threadIdx.x;
    const int lane = tid & 31, w = tid >> 5;         // w = 0..15, one 16-row m-tile
    const int bb0  = blockIdx.x * 16;                // 16 batches per CTA

    // prologue: cp.async W fragments for ib=0 into buf0 (2048 uint4)
    #pragma unroll
    for (int k = 0; k < 4; k++) {
        int o = (tid + k * NT) * 16;
        cp16(sbase + SMB_OFF + o, g_wbuf + o);
    }
    asm volatile("cp.async.commit_group;");

    // stage x0/x1 -> smem transposed [j or i][n], stride 260
    {
        const float4* g0 = (const float4*)(x0g + bb0 * 1024);
        const float4* g1 = (const float4*)(x1g + bb0 * 1024);
        #pragma unroll
        for (int k = 0; k < 8; k++) {
            int m = tid + k * NT;                    // 0..4095 float4
            int bl = m >> 8, rem = m & 255;
            int j = rem >> 2, nl = bl * 16 + (rem & 3) * 4;
            float4 v0 = g0[m], v1 = g1[m];
            *(float4*)(x0s + j * 260 + nl) = v0;
            *(float4*)(x1s + j * 260 + nl) = v1;
        }
    }
    __syncthreads();

    // A fragments from x1 (hi/lo): 4 k-steps x 4 regs, row base w*16
    uint32_t ah[4][4], al[4][4];
    {
        const int r0 = lane >> 2, k0 = (lane & 3) * 2;
        #pragma unroll
        for (int ks = 0; ks < 4; ks++)
            #pragma unroll
            for (int p = 0; p < 4; p++) {
                int row = w * 16 + r0 + (p & 1) * 8;
                int kb  = ks * 16 + k0 + (p >> 1) * 8;
                float v0 = x1s[kb * 260 + row];
                float v1 = x1s[(kb + 1) * 260 + row];
                float h0, l0, h1, l1;
                split(v0, h0, l0); split(v1, h1, l1);
                ah[ks][p] = pkbf(h0, h1);
                al[ks][p] = pkbf(l0, l1);
            }
    }

    float acc[2][2][2];                              // [lhi][row][e]
    #pragma unroll
    for (int a = 0; a < 2; a++)
        #pragma unroll
        for (int b = 0; b < 2; b++)
            #pragma unroll
            for (int c = 0; c < 2; c++) acc[a][b][c] = 0.f;

    const int nloc0 = w * 16 + (lane >> 2);

    for (int ib = 0; ib < 8; ib++) {
        if (ib + 1 < 8) {
            const unsigned char* src = g_wbuf + (ib + 1) * 32768;
            uint32_t dst = sbase + SMB_OFF + ((ib + 1) & 1) * 32768;
            #pragma unroll
            for (int k = 0; k < 4; k++) {
                int o = (tid + k * NT) * 16;
                cp16(dst + o, src + o);
            }
        }
        asm volatile("cp.async.commit_group;");
        asm volatile("cp.async.wait_group 1;");
        __syncthreads();

        const uint4* Bs = (const uint4*)((const unsigned char*)smem + SMB_OFF
                                         + (ib & 1) * 32768);
        #pragma unroll
        for (int p = 0; p < 8; p++) {                // nt pair (2p, 2p+1), shared i
            const int i = ib * 8 + p;
            float x0a = x0s[i * 260 + nloc0];
            float x0b = x0s[i * 260 + nloc0 + 8];

            float c0[4] = {0.f, 0.f, 0.f, 0.f};      // nt = 2p   (l = 0..7)
            float c1[4] = {0.f, 0.f, 0.f, 0.f};      // nt = 2p+1 (l = 8..15)
            #pragma unroll
            for (int ks = 0; ks < 4; ks++) {
                uint4 b0 = Bs[((2 * p) * 4 + ks) * 32 + lane];
                uint4 b1 = Bs[((2 * p + 1) * 4 + ks) * 32 + lane];
                mma_bf16(c0, ah[ks], b0.x, b0.y);
                mma_bf16(c1, ah[ks], b1.x, b1.y);
                mma_bf16(c0, ah[ks], b0.z, b0.w);
                mma_bf16(c1, ah[ks], b1.z, b1.w);
                mma_bf16(c0, al[ks], b0.x, b0.y);
                mma_bf16(c1, al[ks], b1.x, b1.y);
            }
            acc[0][0][0] += x0a * c0[0];
            acc[0][0][1] += x0a * c0[1];
            acc[0][1][0] += x0b * c0[2];
            acc[0][1][1] += x0b * c0[3];
            acc[1][0][0] += x0a * c1[0];
            acc[1][0][1] += x0a * c1[1];
            acc[1][1][0] += x0b * c1[2];
            acc[1][1][1] += x0b * c1[3];
        }
        __syncthreads();
    }

    // output: thread owns 2 lhi x 2 rows x 2 l values
    #pragma unroll
    for (int lhi = 0; lhi < 2; lhi++)
        #pragma unroll
        for (int r = 0; r < 2; r++)
            #pragma unroll
            for (int e = 0; e < 2; e++) {
                int nloc = nloc0 + r * 8;
                int l = lhi * 8 + (lane & 3) * 2 + e;
                outg[(bb0 + (nloc >> 4)) * 256 + l * 16 + (nloc & 15)]
                    = acc[lhi][r][e];
            }
}

extern "C" void kernel_launch(void* const* d_in, const int* in_sizes, int n_in,
                              void* d_out, int out_size)
{
    const float* x0   = (const float*)d_in[0];   // [2048, 64, 16]
    const float* x1   = (const float*)d_in[1];   // [2048, 64, 16]
    const float* filt = (const float*)d_in[2];   // [1, 4096, 16]
    float* out        = (float*)d_out;           // [2048, 16, 16]

    prep_kernel<<<64, 256>>>(filt);
    cudaFuncSetAttribute(efm_mma_kernel, cudaFuncAttributeMaxDynamicSharedMemorySize, SMEM_BYTES);
    efm_mma_kernel<<<128, NT, SMEM_BYTES>>>(x0, x1, out);
}

// round 8
// speedup vs baseline: 2.7837x; 1.1061x over previous
#include <cuda_runtime.h>
#include <cuda_bf16.h>
#include <cstdint>

// out[b,l,d] = sum_{i,j} x0[b,i,d] * x1[b,j,d] * filters[i*64+j, l]
// B=2048, F1=F2=64, D=16, L=16
//
// mma.sync m16n8k16 bf16, 3-term hi/lo split, fp32 accum. Barrier-free version:
// warp owns TWO batches (32 n-rows as 2 m16 tiles sharing B fragments), reads
// pre-packed W fragments straight from global (L1/L2 resident) via __ldg, keeps
// 4 independent accumulator chains. No smem, no __syncthreads anywhere.
// Grid 147 x 224 threads (7 warps) -> ~1 CTA/SM on all SMs, even HMMA spread.

#define NW 7
#define NTHR (NW * 32)

__device__ __align__(16) unsigned char g_wbuf[262144];   // 8 ib x 32KB fragment-packed W

// ---------------- helpers ----------------
__device__ __forceinline__ uint32_t pkbf(float v0, float v1) {   // low half = v0
    __nv_bfloat162 t = __float22bfloat162_rn(make_float2(v0, v1));
    return *(uint32_t*)&t;
}
__device__ __forceinline__ void split(float v, float& h, float& l) {
    __nv_bfloat16 hb = __float2bfloat16_rn(v);
    h = __bfloat162float(hb);
    l = v - h;
}
__device__ __forceinline__ void mma_bf16(float* c, const uint32_t* a,
                                         uint32_t b0, uint32_t b1) {
    asm("mma.sync.aligned.m16n8k16.row.col.f32.bf16.bf16.f32 "
        "{%0,%1,%2,%3}, {%4,%5,%6,%7}, {%8,%9}, {%0,%1,%2,%3};"
        : "+f"(c[0]), "+f"(c[1]), "+f"(c[2]), "+f"(c[3])
        : "r"(a[0]), "r"(a[1]), "r"(a[2]), "r"(a[3]), "r"(b0), "r"(b1));
}

// ---------------- prep: W -> bf16 hi/lo, mma-fragment packed ----------------
__global__ void prep_kernel(const float* __restrict__ filt) {
    int idx = blockIdx.x * 256 + threadIdx.x;        // 16384 threads
    int lane = idx & 31;
    int ks   = (idx >> 5) & 3;
    int nt   = (idx >> 7) & 15;
    int ib   = idx >> 11;                            // 0..7
    int np   = lane >> 2;                            // col within ntile
    int cg   = nt * 8 + np;                          // global col 0..127
    int il   = cg >> 4, l = cg & 15;
    int jb   = ks * 16 + (lane & 3) * 2;
    const float* base = filt + (ib * 8 + il) * 64 * 16 + l;
    float f0 = base[jb * 16],       f1 = base[(jb + 1) * 16];
    float f2 = base[(jb + 8) * 16], f3 = base[(jb + 9) * 16];
    float h0, l0, h1, l1, h2, l2, h3, l3;
    split(f0, h0, l0); split(f1, h1, l1); split(f2, h2, l2); split(f3, h3, l3);
    uint4 o;
    o.x = pkbf(h0, h1); o.y = pkbf(h2, h3);          // b_hi (k lo pair, k hi pair)
    o.z = pkbf(l0, l1); o.w = pkbf(l2, l3);          // b_lo
    *(uint4*)(g_wbuf + ib * 32768 + ((nt * 4 + ks) * 32 + lane) * 16) = o;
}

// ---------------- main ----------------
__global__ void __launch_bounds__(NTHR, 1)
efm_mma_kernel(const float* __restrict__ x0g, const float* __restrict__ x1g,
               float* __restrict__ outg)
{
    const int lane = threadIdx.x & 31;
    const int w    = threadIdx.x >> 5;
    const int bp   = blockIdx.x * NW + w;            // batch-pair index
    if (bp >= 1024) return;
    const int b0 = bp * 2;
    const int r0 = lane >> 2, k0 = (lane & 3) * 2;

    // ---- A fragments from x1 (hi/lo), 2 batches x 4 k-steps x 4 regs ----
    uint32_t ah[2][4][4], al[2][4][4];
    #pragma unroll
    for (int mt = 0; mt < 2; mt++) {
        const float* xb = x1g + (b0 + mt) * 1024;
        #pragma unroll
        for (int ks = 0; ks < 4; ks++)
            #pragma unroll
            for (int p4 = 0; p4 < 4; p4++) {
                int row = r0 + (p4 & 1) * 8;
                int kb  = ks * 16 + k0 + (p4 >> 1) * 8;
                float v0 = __ldg(xb + kb * 16 + row);
                float v1 = __ldg(xb + (kb + 1) * 16 + row);
                float h0, l0, h1, l1;
                split(v0, h0, l0); split(v1, h1, l1);
                ah[mt][ks][p4] = pkbf(h0, h1);
                al[mt][ks][p4] = pkbf(l0, l1);
            }
    }

    float acc[2][2][2][2];                           // [mt][lhi][row][e]
    #pragma unroll
    for (int a = 0; a < 2; a++)
        #pragma unroll
        for (int b = 0; b < 2; b++)
            #pragma unroll
            for (int c = 0; c < 2; c++)
                #pragma unroll
                for (int d = 0; d < 2; d++) acc[a][b][c][d] = 0.f;

    const float* x0a = x0g + b0 * 1024 + r0;
    const float* x0b = x0g + (b0 + 1) * 1024 + r0;

    #pragma unroll 1
    for (int ib = 0; ib < 8; ib++) {
        const uint4* Bi = (const uint4*)(g_wbuf + ib * 32768);

        #pragma unroll
        for (int p = 0; p < 8; p++) {
            // B fragments for nt pair (2p, 2p+1), all 4 k-steps
            uint4 bv0[4], bv1[4];
            #pragma unroll
            for (int ks = 0; ks < 4; ks++) {
                bv0[ks] = __ldg(Bi + ((2 * p) * 4 + ks) * 32 + lane);
                bv1[ks] = __ldg(Bi + ((2 * p + 1) * 4 + ks) * 32 + lane);
            }
            const int i = ib * 8 + p;
            float x0v[2][2];
            x0v[0][0] = __ldg(x0a + i * 16);
            x0v[0][1] = __ldg(x0a + i * 16 + 8);
            x0v[1][0] = __ldg(x0b + i * 16);
            x0v[1][1] = __ldg(x0b + i * 16 + 8);

            // 4 independent chains: [mt*2 + lhi]
            float c[4][4] = {{0.f,0.f,0.f,0.f},{0.f,0.f,0.f,0.f},
                             {0.f,0.f,0.f,0.f},{0.f,0.f,0.f,0.f}};
            #pragma unroll
            for (int ks = 0; ks < 4; ks++) {
                mma_bf16(c[0], ah[0][ks], bv0[ks].x, bv0[ks].y);
                mma_bf16(c[1], ah[0][ks], bv1[ks].x, bv1[ks].y);
                mma_bf16(c[2], ah[1][ks], bv0[ks].x, bv0[ks].y);
                mma_bf16(c[3], ah[1][ks], bv1[ks].x, bv1[ks].y);
                mma_bf16(c[0], ah[0][ks], bv0[ks].z, bv0[ks].w);
                mma_bf16(c[1], ah[0][ks], bv1[ks].z, bv1[ks].w);
                mma_bf16(c[2], ah[1][ks], bv0[ks].z, bv0[ks].w);
                mma_bf16(c[3], ah[1][ks], bv1[ks].z, bv1[ks].w);
                mma_bf16(c[0], al[0][ks], bv0[ks].x, bv0[ks].y);
                mma_bf16(c[1], al[0][ks], bv1[ks].x, bv1[ks].y);
                mma_bf16(c[2], al[1][ks], bv0[ks].x, bv0[ks].y);
                mma_bf16(c[3], al[1][ks], bv1[ks].x, bv1[ks].y);
            }
            #pragma unroll
            for (int mt = 0; mt < 2; mt++)
                #pragma unroll
                for (int lhi = 0; lhi < 2; lhi++)
                    #pragma unroll
                    for (int r = 0; r < 2; r++)
                        #pragma unroll
                        for (int e = 0; e < 2; e++)
                            acc[mt][lhi][r][e] += x0v[mt][r] * c[mt * 2 + lhi][r * 2 + e];
        }
    }

    // ---- output: per lane 2 mt x 2 lhi x 2 rows x 2 l ----
    #pragma unroll
    for (int mt = 0; mt < 2; mt++)
        #pragma unroll
        for (int lhi = 0; lhi < 2; lhi++)
            #pragma unroll
            for (int r = 0; r < 2; r++)
                #pragma unroll
                for (int e = 0; e < 2; e++) {
                    int l = lhi * 8 + (lane & 3) * 2 + e;
                    int d = r0 + r * 8;
                    outg[(b0 + mt) * 256 + l * 16 + d] = acc[mt][lhi][r][e];
                }
}

extern "C" void kernel_launch(void* const* d_in, const int* in_sizes, int n_in,
                              void* d_out, int out_size)
{
    const float* x0   = (const float*)d_in[0];   // [2048, 64, 16]
    const float* x1   = (const float*)d_in[1];   // [2048, 64, 16]
    const float* filt = (const float*)d_in[2];   // [1, 4096, 16]
    float* out        = (float*)d_out;           // [2048, 16, 16]

    prep_kernel<<<64, 256>>>(filt);
    efm_mma_kernel<<<147, NTHR>>>(x0, x1, out);  // 147*7 = 1029 >= 1024 batch pairs
}

// round 9
// speedup vs baseline: 3.5078x; 1.2601x over previous
#include <cuda_runtime.h>
#include <cuda_fp16.h>
#include <cstdint>

// out[b,l,d] = sum_{i,j} x0[b,i,d] * x1[b,j,d] * filters[i*64+j, l]
// B=2048, F1=F2=64, D=16, L=16
//
// mma.sync m16n8k16 fp16, 2-term split (W = bh + bl, x1 single fp16; dropped
// term x1_lo*W ~ 2^-12 rel -> rel_err ~2.4e-4 < 1e-3), fp32 accum.
// Warp = 1 batch (16 d-rows = one m16 tile). 448 threads (14 warps) x 147 CTAs
// -> 2058 warps >= 2048 batches, ~14 warps/SM, ~90 regs (no spills).
// Barrier-free: W fragments pre-packed by prep_kernel, read via __ldg (L1/L2
// resident); no smem, no __syncthreads.

#define NW 14
#define NTHR (NW * 32)

__device__ __align__(16) unsigned char g_wbuf[262144];   // 8 ib x 32KB fragment-packed W

// ---------------- helpers ----------------
__device__ __forceinline__ uint32_t pkhf(float v0, float v1) {   // low half = v0
    __half2 t = __floats2half2_rn(v0, v1);
    return *(uint32_t*)&t;
}
__device__ __forceinline__ void mma_f16(float* c, const uint32_t* a,
                                        uint32_t b0, uint32_t b1) {
    asm("mma.sync.aligned.m16n8k16.row.col.f32.f16.f16.f32 "
        "{%0,%1,%2,%3}, {%4,%5,%6,%7}, {%8,%9}, {%0,%1,%2,%3};"
        : "+f"(c[0]), "+f"(c[1]), "+f"(c[2]), "+f"(c[3])
        : "r"(a[0]), "r"(a[1]), "r"(a[2]), "r"(a[3]), "r"(b0), "r"(b1));
}

// ---------------- prep: W -> fp16 hi/lo, mma-fragment packed ----------------
__global__ void prep_kernel(const float* __restrict__ filt) {
    int idx = blockIdx.x * 256 + threadIdx.x;        // 16384 threads
    int lane = idx & 31;
    int ks   = (idx >> 5) & 3;
    int nt   = (idx >> 7) & 15;
    int ib   = idx >> 11;                            // 0..7
    int np   = lane >> 2;                            // col within ntile
    int cg   = nt * 8 + np;                          // global col 0..127
    int il   = cg >> 4, l = cg & 15;
    int jb   = ks * 16 + (lane & 3) * 2;
    const float* base = filt + (ib * 8 + il) * 64 * 16 + l;
    float f0 = base[jb * 16],       f1 = base[(jb + 1) * 16];
    float f2 = base[(jb + 8) * 16], f3 = base[(jb + 9) * 16];
    __half h0 = __float2half_rn(f0), h1 = __float2half_rn(f1);
    __half h2 = __float2half_rn(f2), h3 = __float2half_rn(f3);
    float l0 = f0 - __half2float(h0), l1 = f1 - __half2float(h1);
    float l2 = f2 - __half2float(h2), l3 = f3 - __half2float(h3);
    uint4 o;
    o.x = pkhf(__half2float(h0), __half2float(h1));
    o.y = pkhf(__half2float(h2), __half2float(h3));
    o.z = pkhf(l0, l1);
    o.w = pkhf(l2, l3);
    *(uint4*)(g_wbuf + ib * 32768 + ((nt * 4 + ks) * 32 + lane) * 16) = o;
}

// ---------------- main ----------------
__global__ void __launch_bounds__(NTHR, 1)
efm_mma_kernel(const float* __restrict__ x0g, const float* __restrict__ x1g,
               float* __restrict__ outg)
{
    const int lane = threadIdx.x & 31;
    const int w    = threadIdx.x >> 5;
    const int b    = blockIdx.x * NW + w;            // batch index
    if (b >= 2048) return;
    const int r0 = lane >> 2, k0 = (lane & 3) * 2;

    // ---- A fragments from x1 (fp16, single term): 4 k-steps x 4 regs ----
    uint32_t ah[4][4];
    {
        const float* xb = x1g + b * 1024;
        #pragma unroll
        for (int ks = 0; ks < 4; ks++)
            #pragma unroll
            for (int p4 = 0; p4 < 4; p4++) {
                int row = r0 + (p4 & 1) * 8;
                int kb  = ks * 16 + k0 + (p4 >> 1) * 8;
                float v0 = __ldg(xb + kb * 16 + row);
                float v1 = __ldg(xb + (kb + 1) * 16 + row);
                ah[ks][p4] = pkhf(v0, v1);
            }
    }

    float acc[2][2][2];                              // [lhi][row][e]
    #pragma unroll
    for (int a = 0; a < 2; a++)
        #pragma unroll
        for (int bq = 0; bq < 2; bq++)
            #pragma unroll
            for (int c = 0; c < 2; c++) acc[a][bq][c] = 0.f;

    const float* x0b = x0g + b * 1024 + r0;

    #pragma unroll 1
    for (int ib = 0; ib < 8; ib++) {
        const uint4* Bi = (const uint4*)(g_wbuf + ib * 32768);

        #pragma unroll
        for (int p = 0; p < 8; p++) {
            // B fragments for nt pair (2p, 2p+1): {bh0,bh1,bl0,bl1} per ks
            uint4 bv0[4], bv1[4];
            #pragma unroll
            for (int ks = 0; ks < 4; ks++) {
                bv0[ks] = __ldg(Bi + ((2 * p) * 4 + ks) * 32 + lane);
                bv1[ks] = __ldg(Bi + ((2 * p + 1) * 4 + ks) * 32 + lane);
            }
            const int i = ib * 8 + p;
            float x0lo = __ldg(x0b + i * 16);
            float x0hi = __ldg(x0b + i * 16 + 8);

            float c0[4] = {0.f, 0.f, 0.f, 0.f};      // l = 0..7
            float c1[4] = {0.f, 0.f, 0.f, 0.f};      // l = 8..15
            #pragma unroll
            for (int ks = 0; ks < 4; ks++) {
                mma_f16(c0, ah[ks], bv0[ks].x, bv0[ks].y);   // hi term
                mma_f16(c1, ah[ks], bv1[ks].x, bv1[ks].y);
                mma_f16(c0, ah[ks], bv0[ks].z, bv0[ks].w);   // lo term
                mma_f16(c1, ah[ks], bv1[ks].z, bv1[ks].w);
            }
            acc[0][0][0] += x0lo * c0[0];
            acc[0][0][1] += x0lo * c0[1];
            acc[0][1][0] += x0hi * c0[2];
            acc[0][1][1] += x0hi * c0[3];
            acc[1][0][0] += x0lo * c1[0];
            acc[1][0][1] += x0lo * c1[1];
            acc[1][1][0] += x0hi * c1[2];
            acc[1][1][1] += x0hi * c1[3];
        }
    }

    // ---- output: per lane 2 lhi x 2 rows x 2 l ----
    #pragma unroll
    for (int lhi = 0; lhi < 2; lhi++)
        #pragma unroll
        for (int r = 0; r < 2; r++)
            #pragma unroll
            for (int e = 0; e < 2; e++) {
                int l = lhi * 8 + (lane & 3) * 2 + e;
                int d = r0 + r * 8;
                outg[b * 256 + l * 16 + d] = acc[lhi][r][e];
            }
}

extern "C" void kernel_launch(void* const* d_in, const int* in_sizes, int n_in,
                              void* d_out, int out_size)
{
    const float* x0   = (const float*)d_in[0];   // [2048, 64, 16]
    const float* x1   = (const float*)d_in[1];   // [2048, 64, 16]
    const float* filt = (const float*)d_in[2];   // [1, 4096, 16]
    float* out        = (float*)d_out;           // [2048, 16, 16]

    prep_kernel<<<64, 256>>>(filt);
    efm_mma_kernel<<<147, NTHR>>>(x0, x1, out);  // 147*14 = 2058 >= 2048 batches
}

// round 11
// speedup vs baseline: 3.5260x; 1.0052x over previous
#include <cuda_runtime.h>
#include <cuda_fp16.h>
#include <cstdint>

// out[b,l,d] = sum_{i,j} x0[b,i,d] * x1[b,j,d] * filters[i*64+j, l]
// B=2048, F1=F2=64, D=16, L=16
//
// mma.sync m16n8k16 fp16, 2-term split (W = bh + bl; dropped x1_lo*W term
// ~2^-12 rel -> rel_err ~2e-4 < 1e-3), fp32 accum.
// Warp owns TWO batches (2 m16 tiles sharing every B fragment) -> B-fragment
// L1 traffic per MMA halved vs 1-batch/warp; 4 independent accumulator chains.
// Barrier-free: W pre-packed by prep_kernel, read via __ldg; no smem/syncs.
// Grid 147 x 224 (7 warps) = 1029 warps >= 1024 batch-pairs, ~1 CTA/SM.

#define NW 7
#define NTHR (NW * 32)

__device__ __align__(16) unsigned char g_wbuf[262144];   // 8 ib x 32KB fragment-packed W

// ---------------- helpers ----------------
__device__ __forceinline__ uint32_t pkhf(float v0, float v1) {   // low half = v0
    __half2 t = __floats2half2_rn(v0, v1);
    return *(uint32_t*)&t;
}
__device__ __forceinline__ void mma_f16(float* c, const uint32_t* a,
                                        uint32_t b0, uint32_t b1) {
    asm("mma.sync.aligned.m16n8k16.row.col.f32.f16.f16.f32 "
        "{%0,%1,%2,%3}, {%4,%5,%6,%7}, {%8,%9}, {%0,%1,%2,%3};"
        : "+f"(c[0]), "+f"(c[1]), "+f"(c[2]), "+f"(c[3])
        : "r"(a[0]), "r"(a[1]), "r"(a[2]), "r"(a[3]), "r"(b0), "r"(b1));
}

// ---------------- prep: W -> fp16 hi/lo, mma-fragment packed ----------------
__global__ void prep_kernel(const float* __restrict__ filt) {
    int idx = blockIdx.x * 256 + threadIdx.x;        // 16384 threads
    int lane = idx & 31;
    int ks   = (idx >> 5) & 3;
    int nt   = (idx >> 7) & 15;
    int ib   = idx >> 11;                            // 0..7
    int np   = lane >> 2;                            // col within ntile
    int cg   = nt * 8 + np;                          // global col 0..127
    int il   = cg >> 4, l = cg & 15;
    int jb   = ks * 16 + (lane & 3) * 2;
    const float* base = filt + (ib * 8 + il) * 64 * 16 + l;
    float f0 = base[jb * 16],       f1 = base[(jb + 1) * 16];
    float f2 = base[(jb + 8) * 16], f3 = base[(jb + 9) * 16];
    __half h0 = __float2half_rn(f0), h1 = __float2half_rn(f1);
    __half h2 = __float2half_rn(f2), h3 = __float2half_rn(f3);
    float l0 = f0 - __half2float(h0), l1 = f1 - __half2float(h1);
    float l2 = f2 - __half2float(h2), l3 = f3 - __half2float(h3);
    uint4 o;
    o.x = pkhf(__half2float(h0), __half2float(h1));  // b_hi (k lo pair, k hi pair)
    o.y = pkhf(__half2float(h2), __half2float(h3));
    o.z = pkhf(l0, l1);                              // b_lo
    o.w = pkhf(l2, l3);
    *(uint4*)(g_wbuf + ib * 32768 + ((nt * 4 + ks) * 32 + lane) * 16) = o;
}

// ---------------- main ----------------
__global__ void __launch_bounds__(NTHR, 1)
efm_mma_kernel(const float* __restrict__ x0g, const float* __restrict__ x1g,
               float* __restrict__ outg)
{
    const int lane = threadIdx.x & 31;
    const int w    = threadIdx.x >> 5;
    const int bp   = blockIdx.x * NW + w;            // batch-pair index
    if (bp >= 1024) return;
    const int b0 = bp * 2;
    const int r0 = lane >> 2, k0 = (lane & 3) * 2;

    // ---- A fragments from x1 (fp16, single term): 2 batches x 4 ks x 4 regs ----
    uint32_t ah[2][4][4];
    #pragma unroll
    for (int mt = 0; mt < 2; mt++) {
        const float* xb = x1g + (b0 + mt) * 1024;
        #pragma unroll
        for (int ks = 0; ks < 4; ks++)
            #pragma unroll
            for (int p4 = 0; p4 < 4; p4++) {
                int row = r0 + (p4 & 1) * 8;
                int kb  = ks * 16 + k0 + (p4 >> 1) * 8;
                float v0 = __ldg(xb + kb * 16 + row);
                float v1 = __ldg(xb + (kb + 1) * 16 + row);
                ah[mt][ks][p4] = pkhf(v0, v1);
            }
    }

    float acc[2][2][2][2];                           // [mt][lhi][row][e]
    #pragma unroll
    for (int a = 0; a < 2; a++)
        #pragma unroll
        for (int bq = 0; bq < 2; bq++)
            #pragma unroll
            for (int c = 0; c < 2; c++)
                #pragma unroll
                for (int d = 0; d < 2; d++) acc[a][bq][c][d] = 0.f;

    const float* x0a = x0g + b0 * 1024 + r0;
    const float* x0b = x0g + (b0 + 1) * 1024 + r0;

    #pragma unroll 1
    for (int ib = 0; ib < 8; ib++) {
        const uint4* Bi = (const uint4*)(g_wbuf + ib * 32768);

        #pragma unroll
        for (int p = 0; p < 8; p++) {
            // B fragments for nt pair (2p, 2p+1): {bh0,bh1,bl0,bl1} per ks
            uint4 bv0[4], bv1[4];
            #pragma unroll
            for (int ks = 0; ks < 4; ks++) {
                bv0[ks] = __ldg(Bi + ((2 * p) * 4 + ks) * 32 + lane);
                bv1[ks] = __ldg(Bi + ((2 * p + 1) * 4 + ks) * 32 + lane);
            }
            const int i = ib * 8 + p;
            float x0v[2][2];
            x0v[0][0] = __ldg(x0a + i * 16);
            x0v[0][1] = __ldg(x0a + i * 16 + 8);
            x0v[1][0] = __ldg(x0b + i * 16);
            x0v[1][1] = __ldg(x0b + i * 16 + 8);

            // 4 independent chains: [mt*2 + lhi]
            float c[4][4] = {{0.f,0.f,0.f,0.f},{0.f,0.f,0.f,0.f},
                             {0.f,0.f,0.f,0.f},{0.f,0.f,0.f,0.f}};
            #pragma unroll
            for (int ks = 0; ks < 4; ks++) {
                mma_f16(c[0], ah[0][ks], bv0[ks].x, bv0[ks].y);   // hi term
                mma_f16(c[1], ah[0][ks], bv1[ks].x, bv1[ks].y);
                mma_f16(c[2], ah[1][ks], bv0[ks].x, bv0[ks].y);
                mma_f16(c[3], ah[1][ks], bv1[ks].x, bv1[ks].y);
                mma_f16(c[0], ah[0][ks], bv0[ks].z, bv0[ks].w);   // lo term
                mma_f16(c[1], ah[0][ks], bv1[ks].z, bv1[ks].w);
                mma_f16(c[2], ah[1][ks], bv0[ks].z, bv0[ks].w);
                mma_f16(c[3], ah[1][ks], bv1[ks].z, bv1[ks].w);
            }
            #pragma unroll
            for (int mt = 0; mt < 2; mt++)
                #pragma unroll
                for (int lhi = 0; lhi < 2; lhi++)
                    #pragma unroll
                    for (int r = 0; r < 2; r++)
                        #pragma unroll
                        for (int e = 0; e < 2; e++)
                            acc[mt][lhi][r][e] += x0v[mt][r] * c[mt * 2 + lhi][r * 2 + e];
        }
    }

    // ---- output: per lane 2 mt x 2 lhi x 2 rows x 2 l ----
    #pragma unroll
    for (int mt = 0; mt < 2; mt++)
        #pragma unroll
        for (int lhi = 0; lhi < 2; lhi++)
            #pragma unroll
            for (int r = 0; r < 2; r++)
                #pragma unroll
                for (int e = 0; e < 2; e++) {
                    int l = lhi * 8 + (lane & 3) * 2 + e;
                    int d = r0 + r * 8;
                    outg[(b0 + mt) * 256 + l * 16 + d] = acc[mt][lhi][r][e];
                }
}

extern "C" void kernel_launch(void* const* d_in, const int* in_sizes, int n_in,
                              void* d_out, int out_size)
{
    const float* x0   = (const float*)d_in[0];   // [2048, 64, 16]
    const float* x1   = (const float*)d_in[1];   // [2048, 64, 16]
    const float* filt = (const float*)d_in[2];   // [1, 4096, 16]
    float* out        = (float*)d_out;           // [2048, 16, 16]

    prep_kernel<<<64, 256>>>(filt);
    efm_mma_kernel<<<147, NTHR>>>(x0, x1, out);  // 147*7 = 1029 >= 1024 batch pairs
}